// round 14
// baseline (speedup 1.0000x reference)
#include <cuda_runtime.h>
#include <cstdint>

#define N_NODES   1048576
#define N_GRAPHS  1024
#define F_X       128
#define F_U       128
#define F_CAT     256
#define HIDDEN    512
#define F_OUT     128

// Scratch (allocation-free rule: __device__ globals)
__device__ float g_concat[N_GRAPHS * F_CAT];   // [1024,256] = x_agg || u
__device__ float g_h[N_GRAPHS * HIDDEN];       // [1024,512]

// ---------------------------------------------------------------------------
// Warp-collective lower_bound on sorted int array: 32-ary search.
// ---------------------------------------------------------------------------
__device__ __forceinline__ int warp_lower_bound(const int* __restrict__ batch,
                                                int target, int lane) {
    int lo = 0, hi = N_NODES;              // answer in [lo, hi]
    while (hi - lo > 32) {
        int step = (hi - lo) >> 5;         // >= 1
        int pos  = lo + lane * step;
        int v    = __ldg(batch + pos);
        unsigned mask = __ballot_sync(0xffffffffu, v < target);
        if (mask == 0) {
            hi = lo + step;
        } else {
            int istar = 31 - __clz(mask);
            int nlo   = lo + istar * step;
            int nhi   = (istar < 31) ? (nlo + step) : hi;
            lo = nlo; hi = nhi;
        }
    }
    int pos = lo + lane;
    int v   = (pos < hi) ? __ldg(batch + pos) : 0x7fffffff;
    unsigned mask = __ballot_sync(0xffffffffu, (pos < hi) && (v < target));
    return lo + __popc(mask);
}

// ---------------------------------------------------------------------------
// 1) Segment mean of x -> g_concat[:,0:128]; u -> g_concat[:,128:256].
//    One block per graph, 256 threads; single wave; at the spr_max floor.
// ---------------------------------------------------------------------------
__global__ void __launch_bounds__(256, 8) seg_mean_kernel(const float* __restrict__ x,
                                                          const float* __restrict__ u,
                                                          const int*   __restrict__ batch) {
    const int g    = blockIdx.x;
    const int tid  = threadIdx.x;
    const int lane = tid & 31;   // feature quad
    const int grp  = tid >> 5;   // row group 0..7

    __shared__ int s_se[2];
    if (grp < 2) {               // warp 0 -> start, warp 1 -> end
        int r = warp_lower_bound(batch, g + grp, lane);
        if (lane == 0) s_se[grp] = r;
    }
    __syncthreads();
    const int start = s_se[0];
    const int end   = s_se[1];

    const float* xb = x + (size_t)lane * 4;

    float4 a0 = {0,0,0,0}, a1 = {0,0,0,0};
    int r = start + grp;
    for (; r + 8 < end; r += 16) {      // 2 loads in flight per thread
        float4 v0 = __ldcs((const float4*)(xb + (size_t)(r    ) * F_X));
        float4 v1 = __ldcs((const float4*)(xb + (size_t)(r + 8) * F_X));
        a0.x += v0.x; a0.y += v0.y; a0.z += v0.z; a0.w += v0.w;
        a1.x += v1.x; a1.y += v1.y; a1.z += v1.z; a1.w += v1.w;
    }
    if (r < end) {
        float4 v = __ldcs((const float4*)(xb + (size_t)r * F_X));
        a0.x += v.x; a0.y += v.y; a0.z += v.z; a0.w += v.w;
    }
    a0.x += a1.x; a0.y += a1.y; a0.z += a1.z; a0.w += a1.w;

    __shared__ float4 sm[8][32];
    sm[grp][lane] = a0;
    __syncthreads();
    #pragma unroll
    for (int s = 4; s > 0; s >>= 1) {
        if (grp < s) {
            float4 a = sm[grp][lane];
            float4 b = sm[grp + s][lane];
            a.x += b.x; a.y += b.y; a.z += b.z; a.w += b.w;
            sm[grp][lane] = a;
        }
        __syncthreads();
    }

    if (grp == 0) {
        int cnt = end - start;
        float inv = (cnt > 0) ? (1.0f / (float)cnt) : 0.0f;
        float4 a = sm[0][lane];
        a.x *= inv; a.y *= inv; a.z *= inv; a.w *= inv;
        *(float4*)(g_concat + (size_t)g * F_CAT + lane * 4) = a;
    } else if (grp == 1) {
        float4 v = *(const float4*)(u + (size_t)g * F_U + lane * 4);
        *(float4*)(g_concat + (size_t)g * F_CAT + F_X + lane * 4) = v;
    }
}

// ---------------------------------------------------------------------------
// tf32 helpers
// ---------------------------------------------------------------------------
__device__ __forceinline__ float to_tf32(float f) {
    uint32_t u;
    asm("cvt.rna.tf32.f32 %0, %1;" : "=r"(u) : "f"(f));
    return __uint_as_float(u);
}

__device__ __forceinline__ void mma_tf32(float d[4],
                                         uint32_t a0, uint32_t a1, uint32_t a2, uint32_t a3,
                                         uint32_t b0, uint32_t b1) {
    asm("mma.sync.aligned.m16n8k8.row.col.f32.tf32.tf32.f32 "
        "{%0,%1,%2,%3}, {%4,%5,%6,%7}, {%8,%9}, {%0,%1,%2,%3};"
        : "+f"(d[0]), "+f"(d[1]), "+f"(d[2]), "+f"(d[3])
        : "r"(a0), "r"(a1), "r"(a2), "r"(a3), "r"(b0), "r"(b1));
}

// ---------------------------------------------------------------------------
// 2) GEMM1 via tf32 tensor cores: h = relu(concat @ W1 + b1).
//    M=1024, N=512, K=256. Block = 128 threads (4 warps), 64x64 tile, BK=16.
//    Warp grid 2x2; each warp computes 32x32 = 2 m-tiles x 4 n-tiles of
//    m16n8k8 mma. A/B staged in smem pre-converted to tf32 (cvt.rna).
//    Grid = 8 x 16 = 128 blocks. rel_err budget: tf32 ~1e-4 << 1e-3.
// ---------------------------------------------------------------------------
__global__ void __launch_bounds__(128) gemm1_tf32_kernel(const float* __restrict__ A,
                                                         const float* __restrict__ B,
                                                         const float* __restrict__ bias,
                                                         float* __restrict__ C) {
    constexpr int K = F_CAT, N = HIDDEN;

    __shared__ float As[64][20];   // [row][k], pad 20 -> conflict-spread, 16B-aligned rows
    __shared__ float Bs[16][68];   // [k][col], pad 68 -> k varies bank by 4

    const int bm   = blockIdx.y * 64;
    const int bn   = blockIdx.x * 64;
    const int tid  = threadIdx.x;
    const int wid  = tid >> 5;
    const int lane = tid & 31;
    const int gid  = lane >> 2;    // groupID 0..7
    const int tig  = lane & 3;     // thread-in-group 0..3
    const int wm   = (wid >> 1) * 32;   // warp m offset
    const int wn   = (wid & 1) * 32;    // warp n offset

    float d[2][4][4] = {};         // [mtile][ntile][reg]

    for (int k0 = 0; k0 < K; k0 += 16) {
        // A tile 64x16: 256 float4 -> 2 per thread, converted to tf32
        #pragma unroll
        for (int i = 0; i < 2; i++) {
            int idx  = tid + 128 * i;
            int row  = idx >> 2;
            int quad = idx & 3;
            float4 v = *(const float4*)(A + (size_t)(bm + row) * K + k0 + quad * 4);
            As[row][quad * 4 + 0] = to_tf32(v.x);
            As[row][quad * 4 + 1] = to_tf32(v.y);
            As[row][quad * 4 + 2] = to_tf32(v.z);
            As[row][quad * 4 + 3] = to_tf32(v.w);
        }
        // B tile 16x64: 256 float4 -> 2 per thread
        #pragma unroll
        for (int i = 0; i < 2; i++) {
            int idx  = tid + 128 * i;
            int row  = idx >> 4;
            int quad = idx & 15;
            float4 v = *(const float4*)(B + (size_t)(k0 + row) * N + bn + quad * 4);
            Bs[row][quad * 4 + 0] = to_tf32(v.x);
            Bs[row][quad * 4 + 1] = to_tf32(v.y);
            Bs[row][quad * 4 + 2] = to_tf32(v.z);
            Bs[row][quad * 4 + 3] = to_tf32(v.w);
        }
        __syncthreads();

        #pragma unroll
        for (int ks = 0; ks < 16; ks += 8) {
            uint32_t a[2][4];
            #pragma unroll
            for (int mt = 0; mt < 2; mt++) {
                int r0 = wm + mt * 16 + gid;
                a[mt][0] = __float_as_uint(As[r0    ][ks + tig    ]);
                a[mt][1] = __float_as_uint(As[r0 + 8][ks + tig    ]);
                a[mt][2] = __float_as_uint(As[r0    ][ks + tig + 4]);
                a[mt][3] = __float_as_uint(As[r0 + 8][ks + tig + 4]);
            }
            uint32_t b[4][2];
            #pragma unroll
            for (int nt = 0; nt < 4; nt++) {
                int c0 = wn + nt * 8 + gid;
                b[nt][0] = __float_as_uint(Bs[ks + tig    ][c0]);
                b[nt][1] = __float_as_uint(Bs[ks + tig + 4][c0]);
            }
            #pragma unroll
            for (int mt = 0; mt < 2; mt++)
                #pragma unroll
                for (int nt = 0; nt < 4; nt++)
                    mma_tf32(d[mt][nt], a[mt][0], a[mt][1], a[mt][2], a[mt][3],
                             b[nt][0], b[nt][1]);
        }
        __syncthreads();
    }

    // Epilogue: bias + relu. d regs: {0,1}=row gid, cols 2*tig,2*tig+1;
    //                        {2,3}=row gid+8, same cols.
    #pragma unroll
    for (int mt = 0; mt < 2; mt++) {
        #pragma unroll
        for (int nt = 0; nt < 4; nt++) {
            int row = bm + wm + mt * 16 + gid;
            int col = bn + wn + nt * 8 + tig * 2;
            float2 bv = *(const float2*)(bias + col);
            float2 o0 = {fmaxf(d[mt][nt][0] + bv.x, 0.0f),
                         fmaxf(d[mt][nt][1] + bv.y, 0.0f)};
            float2 o1 = {fmaxf(d[mt][nt][2] + bv.x, 0.0f),
                         fmaxf(d[mt][nt][3] + bv.y, 0.0f)};
            *(float2*)(C + (size_t)row       * N + col) = o0;
            *(float2*)(C + (size_t)(row + 8) * N + col) = o1;
        }
    }
}

// ---------------------------------------------------------------------------
// 3) GEMM2 with 4-way in-block split-K: out = h @ W2 + b2. (R13 config)
// ---------------------------------------------------------------------------
__global__ void __launch_bounds__(256) gemm2_kernel(const float* __restrict__ A,
                                                    const float* __restrict__ B,
                                                    const float* __restrict__ bias,
                                                    float* __restrict__ C) {
    constexpr int K = HIDDEN, N = F_OUT, BM = 32, BN = 32, BK = 16, KP = K / 4;

    __shared__ float As[4][BK][BM + 4];
    __shared__ float Bs[4][BK][BN];
    __shared__ float red[3][BM][BN + 4];

    const int bm   = blockIdx.y * BM;
    const int bn   = blockIdx.x * BN;
    const int tid  = threadIdx.x;
    const int ks   = tid >> 6;           // k-slice 0..3
    const int ctid = tid & 63;
    const int tx   = ctid & 7;           // along N (TN=4)
    const int ty   = ctid >> 3;          // along M (TM=4)

    float acc[4][4] = {};

    const int kbeg = ks * KP;
    for (int k0 = kbeg; k0 < kbeg + KP; k0 += BK) {
        #pragma unroll
        for (int i = 0; i < 2; i++) {    // A slice-tile: 32x16 = 128 float4
            int idx  = ctid + 64 * i;
            int row  = idx >> 2;
            int quad = idx & 3;
            float4 v = *(const float4*)(A + (size_t)(bm + row) * K + k0 + quad * 4);
            As[ks][quad * 4 + 0][row] = v.x;
            As[ks][quad * 4 + 1][row] = v.y;
            As[ks][quad * 4 + 2][row] = v.z;
            As[ks][quad * 4 + 3][row] = v.w;
        }
        #pragma unroll
        for (int i = 0; i < 2; i++) {    // B slice-tile: 16x32 = 128 float4
            int idx  = ctid + 64 * i;
            int row  = idx >> 3;
            int quad = idx & 7;
            *(float4*)&Bs[ks][row][quad * 4] =
                *(const float4*)(B + (size_t)(k0 + row) * N + bn + quad * 4);
        }
        __syncthreads();

        float4 a4 = *(const float4*)&As[ks][0][ty * 4];
        float4 b4 = *(const float4*)&Bs[ks][0][tx * 4];
        #pragma unroll
        for (int k = 0; k < BK; k++) {
            float4 a4n = a4, b4n = b4;
            if (k + 1 < BK) {
                a4n = *(const float4*)&As[ks][k + 1][ty * 4];
                b4n = *(const float4*)&Bs[ks][k + 1][tx * 4];
            }
            float a[4] = {a4.x, a4.y, a4.z, a4.w};
            float b[4] = {b4.x, b4.y, b4.z, b4.w};
            #pragma unroll
            for (int i = 0; i < 4; i++)
                #pragma unroll
                for (int j = 0; j < 4; j++)
                    acc[i][j] = fmaf(a[i], b[j], acc[i][j]);
            a4 = a4n; b4 = b4n;
        }
        __syncthreads();
    }

    if (ks > 0) {
        #pragma unroll
        for (int i = 0; i < 4; i++)
            #pragma unroll
            for (int j = 0; j < 4; j++)
                red[ks - 1][ty * 4 + i][tx * 4 + j] = acc[i][j];
    }
    __syncthreads();

    if (ks == 0) {
        float4 bv = *(const float4*)(bias + bn + tx * 4);
        #pragma unroll
        for (int i = 0; i < 4; i++) {
            int row = bm + ty * 4 + i;
            float o[4];
            #pragma unroll
            for (int j = 0; j < 4; j++) {
                float s = acc[i][j];
                s += red[0][ty * 4 + i][tx * 4 + j];
                s += red[1][ty * 4 + i][tx * 4 + j];
                s += red[2][ty * 4 + i][tx * 4 + j];
                o[j] = s;
            }
            float4 ov = {o[0] + bv.x, o[1] + bv.y, o[2] + bv.z, o[3] + bv.w};
            *(float4*)(C + (size_t)row * N + bn + tx * 4) = ov;
        }
    }
}

// ---------------------------------------------------------------------------
// Launch. Inputs: x, edge_index, edge_attr, u, batch, W1, b1, W2, b2.
// edge_* unused; int64 inputs arrive as int32 on device.
// ---------------------------------------------------------------------------
extern "C" void kernel_launch(void* const* d_in, const int* in_sizes, int n_in,
                              void* d_out, int out_size) {
    const float* x     = (const float*)d_in[0];
    const float* u     = (const float*)d_in[3];
    const int*   batch = (const int*)d_in[4];
    const float* W1    = (const float*)d_in[5];
    const float* b1    = (const float*)d_in[6];
    const float* W2    = (const float*)d_in[7];
    const float* b2    = (const float*)d_in[8];
    float*       out   = (float*)d_out;

    void *p_concat = nullptr, *p_h = nullptr;
    cudaGetSymbolAddress(&p_concat, g_concat);
    cudaGetSymbolAddress(&p_h, g_h);

    // 1) segment mean + concat (warp-parallel bounds search), single wave
    seg_mean_kernel<<<N_GRAPHS, 256>>>(x, u, batch);

    // 2) h = relu(concat @ W1 + b1): tf32 tensor cores, 64x64 tiles, grid 128
    gemm1_tf32_kernel<<<dim3(HIDDEN / 64, N_GRAPHS / 64), 128>>>(
        (const float*)p_concat, W1, b1, (float*)p_h);

    // 3) out = h @ W2 + b2: 32x32 tiles, 4-way in-block split-K, grid 128
    gemm2_kernel<<<dim3(F_OUT / 32, N_GRAPHS / 32), 256>>>(
        (const float*)p_h, W2, b2, out);
}

// round 15
// speedup vs baseline: 1.0272x; 1.0272x over previous
#include <cuda_runtime.h>
#include <cstdint>

#define N_NODES   1048576
#define N_GRAPHS  1024
#define F_X       128
#define F_U       128
#define F_CAT     256
#define HIDDEN    512
#define F_OUT     128

// Scratch (allocation-free rule: __device__ globals)
__device__ float g_concat[N_GRAPHS * F_CAT];   // [1024,256] = x_agg || u
__device__ float g_h[N_GRAPHS * HIDDEN];       // [1024,512]

// ---------------------------------------------------------------------------
// Warp-collective lower_bound on sorted int array: 32-ary search.
// ---------------------------------------------------------------------------
__device__ __forceinline__ int warp_lower_bound(const int* __restrict__ batch,
                                                int target, int lane) {
    int lo = 0, hi = N_NODES;              // answer in [lo, hi]
    while (hi - lo > 32) {
        int step = (hi - lo) >> 5;         // >= 1
        int pos  = lo + lane * step;
        int v    = __ldg(batch + pos);
        unsigned mask = __ballot_sync(0xffffffffu, v < target);
        if (mask == 0) {
            hi = lo + step;
        } else {
            int istar = 31 - __clz(mask);
            int nlo   = lo + istar * step;
            int nhi   = (istar < 31) ? (nlo + step) : hi;
            lo = nlo; hi = nhi;
        }
    }
    int pos = lo + lane;
    int v   = (pos < hi) ? __ldg(batch + pos) : 0x7fffffff;
    unsigned mask = __ballot_sync(0xffffffffu, (pos < hi) && (v < target));
    return lo + __popc(mask);
}

// ---------------------------------------------------------------------------
// 1) Segment mean of x -> g_concat[:,0:128]; u -> g_concat[:,128:256].
//    One block per graph, 256 threads; single wave; at the spr_max floor.
// ---------------------------------------------------------------------------
__global__ void __launch_bounds__(256, 8) seg_mean_kernel(const float* __restrict__ x,
                                                          const float* __restrict__ u,
                                                          const int*   __restrict__ batch) {
    const int g    = blockIdx.x;
    const int tid  = threadIdx.x;
    const int lane = tid & 31;   // feature quad
    const int grp  = tid >> 5;   // row group 0..7

    __shared__ int s_se[2];
    if (grp < 2) {               // warp 0 -> start, warp 1 -> end
        int r = warp_lower_bound(batch, g + grp, lane);
        if (lane == 0) s_se[grp] = r;
    }
    __syncthreads();
    const int start = s_se[0];
    const int end   = s_se[1];

    const float* xb = x + (size_t)lane * 4;

    float4 a0 = {0,0,0,0}, a1 = {0,0,0,0};
    int r = start + grp;
    for (; r + 8 < end; r += 16) {      // 2 loads in flight per thread
        float4 v0 = __ldcs((const float4*)(xb + (size_t)(r    ) * F_X));
        float4 v1 = __ldcs((const float4*)(xb + (size_t)(r + 8) * F_X));
        a0.x += v0.x; a0.y += v0.y; a0.z += v0.z; a0.w += v0.w;
        a1.x += v1.x; a1.y += v1.y; a1.z += v1.z; a1.w += v1.w;
    }
    if (r < end) {
        float4 v = __ldcs((const float4*)(xb + (size_t)r * F_X));
        a0.x += v.x; a0.y += v.y; a0.z += v.z; a0.w += v.w;
    }
    a0.x += a1.x; a0.y += a1.y; a0.z += a1.z; a0.w += a1.w;

    __shared__ float4 sm[8][32];
    sm[grp][lane] = a0;
    __syncthreads();
    #pragma unroll
    for (int s = 4; s > 0; s >>= 1) {
        if (grp < s) {
            float4 a = sm[grp][lane];
            float4 b = sm[grp + s][lane];
            a.x += b.x; a.y += b.y; a.z += b.z; a.w += b.w;
            sm[grp][lane] = a;
        }
        __syncthreads();
    }

    if (grp == 0) {
        int cnt = end - start;
        float inv = (cnt > 0) ? (1.0f / (float)cnt) : 0.0f;
        float4 a = sm[0][lane];
        a.x *= inv; a.y *= inv; a.z *= inv; a.w *= inv;
        *(float4*)(g_concat + (size_t)g * F_CAT + lane * 4) = a;
    } else if (grp == 1) {
        float4 v = *(const float4*)(u + (size_t)g * F_U + lane * 4);
        *(float4*)(g_concat + (size_t)g * F_CAT + F_X + lane * 4) = v;
    }
}

// ---------------------------------------------------------------------------
// tf32 helpers
// ---------------------------------------------------------------------------
__device__ __forceinline__ float to_tf32(float f) {
    uint32_t u;
    asm("cvt.rna.tf32.f32 %0, %1;" : "=r"(u) : "f"(f));
    return __uint_as_float(u);
}

__device__ __forceinline__ void mma_tf32(float d[4],
                                         uint32_t a0, uint32_t a1, uint32_t a2, uint32_t a3,
                                         uint32_t b0, uint32_t b1) {
    asm("mma.sync.aligned.m16n8k8.row.col.f32.tf32.tf32.f32 "
        "{%0,%1,%2,%3}, {%4,%5,%6,%7}, {%8,%9}, {%0,%1,%2,%3};"
        : "+f"(d[0]), "+f"(d[1]), "+f"(d[2]), "+f"(d[3])
        : "r"(a0), "r"(a1), "r"(a2), "r"(a3), "r"(b0), "r"(b1));
}

// ---------------------------------------------------------------------------
// 2) GEMM1 via tf32 tensor cores: h = relu(concat @ W1 + b1).
//    M=1024, N=512, K=256. Block = 256 threads (8 warps), 64x64 tile, BK=32.
//    Warp grid 4m x 2n; each warp computes 16x32 = 1 m-tile x 4 n-tiles of
//    m16n8k8 mma -> 2 warps/SMSP cover LDS-gather and mma latency.
//    Grid = 8 x 16 = 128 blocks.
// ---------------------------------------------------------------------------
__global__ void __launch_bounds__(256) gemm1_tf32_kernel(const float* __restrict__ A,
                                                         const float* __restrict__ B,
                                                         const float* __restrict__ bias,
                                                         float* __restrict__ C) {
    constexpr int K = F_CAT, N = HIDDEN;
    constexpr int BK = 32;

    __shared__ float As[64][BK + 4];   // [row][k], pad -> conflict-spread
    __shared__ float Bs[BK][68];       // [k][col], pad 68

    const int bm   = blockIdx.y * 64;
    const int bn   = blockIdx.x * 64;
    const int tid  = threadIdx.x;
    const int wid  = tid >> 5;
    const int lane = tid & 31;
    const int gid  = lane >> 2;        // groupID 0..7
    const int tig  = lane & 3;         // thread-in-group 0..3
    const int wm   = (wid >> 1) * 16;  // warp m offset (4 rows of warps)
    const int wn   = (wid & 1) * 32;   // warp n offset (2 cols of warps)

    float d[4][4] = {};                // [ntile][reg]

    for (int k0 = 0; k0 < K; k0 += BK) {
        // A tile 64x32: 512 float4 -> 2 per thread, converted to tf32
        #pragma unroll
        for (int i = 0; i < 2; i++) {
            int idx  = tid + 256 * i;
            int row  = idx >> 3;           // 64 rows, 8 quads per row
            int quad = idx & 7;
            float4 v = *(const float4*)(A + (size_t)(bm + row) * K + k0 + quad * 4);
            As[row][quad * 4 + 0] = to_tf32(v.x);
            As[row][quad * 4 + 1] = to_tf32(v.y);
            As[row][quad * 4 + 2] = to_tf32(v.z);
            As[row][quad * 4 + 3] = to_tf32(v.w);
        }
        // B tile 32x64: 512 float4 -> 2 per thread
        #pragma unroll
        for (int i = 0; i < 2; i++) {
            int idx  = tid + 256 * i;
            int row  = idx >> 4;           // 32 rows, 16 quads per row
            int quad = idx & 15;
            float4 v = *(const float4*)(B + (size_t)(k0 + row) * N + bn + quad * 4);
            Bs[row][quad * 4 + 0] = to_tf32(v.x);
            Bs[row][quad * 4 + 1] = to_tf32(v.y);
            Bs[row][quad * 4 + 2] = to_tf32(v.z);
            Bs[row][quad * 4 + 3] = to_tf32(v.w);
        }
        __syncthreads();

        #pragma unroll
        for (int ks = 0; ks < BK; ks += 8) {
            uint32_t a[4];
            {
                int r0 = wm + gid;
                a[0] = __float_as_uint(As[r0    ][ks + tig    ]);
                a[1] = __float_as_uint(As[r0 + 8][ks + tig    ]);
                a[2] = __float_as_uint(As[r0    ][ks + tig + 4]);
                a[3] = __float_as_uint(As[r0 + 8][ks + tig + 4]);
            }
            uint32_t b[4][2];
            #pragma unroll
            for (int nt = 0; nt < 4; nt++) {
                int c0 = wn + nt * 8 + gid;
                b[nt][0] = __float_as_uint(Bs[ks + tig    ][c0]);
                b[nt][1] = __float_as_uint(Bs[ks + tig + 4][c0]);
            }
            #pragma unroll
            for (int nt = 0; nt < 4; nt++)
                mma_tf32(d[nt], a[0], a[1], a[2], a[3], b[nt][0], b[nt][1]);
        }
        __syncthreads();
    }

    // Epilogue: bias + relu. regs {0,1}=row gid, {2,3}=row gid+8, cols 2*tig(+1).
    #pragma unroll
    for (int nt = 0; nt < 4; nt++) {
        int row = bm + wm + gid;
        int col = bn + wn + nt * 8 + tig * 2;
        float2 bv = *(const float2*)(bias + col);
        float2 o0 = {fmaxf(d[nt][0] + bv.x, 0.0f),
                     fmaxf(d[nt][1] + bv.y, 0.0f)};
        float2 o1 = {fmaxf(d[nt][2] + bv.x, 0.0f),
                     fmaxf(d[nt][3] + bv.y, 0.0f)};
        *(float2*)(C + (size_t)row       * N + col) = o0;
        *(float2*)(C + (size_t)(row + 8) * N + col) = o1;
    }
}

// ---------------------------------------------------------------------------
// 3) GEMM2 with 4-way in-block split-K: out = h @ W2 + b2. (R13 config,
//    fp32 SIMT — kept to preserve the rel_err margin.)
// ---------------------------------------------------------------------------
__global__ void __launch_bounds__(256) gemm2_kernel(const float* __restrict__ A,
                                                    const float* __restrict__ B,
                                                    const float* __restrict__ bias,
                                                    float* __restrict__ C) {
    constexpr int K = HIDDEN, N = F_OUT, BM = 32, BN = 32, BK = 16, KP = K / 4;

    __shared__ float As[4][BK][BM + 4];
    __shared__ float Bs[4][BK][BN];
    __shared__ float red[3][BM][BN + 4];

    const int bm   = blockIdx.y * BM;
    const int bn   = blockIdx.x * BN;
    const int tid  = threadIdx.x;
    const int ks   = tid >> 6;           // k-slice 0..3
    const int ctid = tid & 63;
    const int tx   = ctid & 7;           // along N (TN=4)
    const int ty   = ctid >> 3;          // along M (TM=4)

    float acc[4][4] = {};

    const int kbeg = ks * KP;
    for (int k0 = kbeg; k0 < kbeg + KP; k0 += BK) {
        #pragma unroll
        for (int i = 0; i < 2; i++) {    // A slice-tile: 32x16 = 128 float4
            int idx  = ctid + 64 * i;
            int row  = idx >> 2;
            int quad = idx & 3;
            float4 v = *(const float4*)(A + (size_t)(bm + row) * K + k0 + quad * 4);
            As[ks][quad * 4 + 0][row] = v.x;
            As[ks][quad * 4 + 1][row] = v.y;
            As[ks][quad * 4 + 2][row] = v.z;
            As[ks][quad * 4 + 3][row] = v.w;
        }
        #pragma unroll
        for (int i = 0; i < 2; i++) {    // B slice-tile: 16x32 = 128 float4
            int idx  = ctid + 64 * i;
            int row  = idx >> 3;
            int quad = idx & 7;
            *(float4*)&Bs[ks][row][quad * 4] =
                *(const float4*)(B + (size_t)(k0 + row) * N + bn + quad * 4);
        }
        __syncthreads();

        float4 a4 = *(const float4*)&As[ks][0][ty * 4];
        float4 b4 = *(const float4*)&Bs[ks][0][tx * 4];
        #pragma unroll
        for (int k = 0; k < BK; k++) {
            float4 a4n = a4, b4n = b4;
            if (k + 1 < BK) {
                a4n = *(const float4*)&As[ks][k + 1][ty * 4];
                b4n = *(const float4*)&Bs[ks][k + 1][tx * 4];
            }
            float a[4] = {a4.x, a4.y, a4.z, a4.w};
            float b[4] = {b4.x, b4.y, b4.z, b4.w};
            #pragma unroll
            for (int i = 0; i < 4; i++)
                #pragma unroll
                for (int j = 0; j < 4; j++)
                    acc[i][j] = fmaf(a[i], b[j], acc[i][j]);
            a4 = a4n; b4 = b4n;
        }
        __syncthreads();
    }

    if (ks > 0) {
        #pragma unroll
        for (int i = 0; i < 4; i++)
            #pragma unroll
            for (int j = 0; j < 4; j++)
                red[ks - 1][ty * 4 + i][tx * 4 + j] = acc[i][j];
    }
    __syncthreads();

    if (ks == 0) {
        float4 bv = *(const float4*)(bias + bn + tx * 4);
        #pragma unroll
        for (int i = 0; i < 4; i++) {
            int row = bm + ty * 4 + i;
            float o[4];
            #pragma unroll
            for (int j = 0; j < 4; j++) {
                float s = acc[i][j];
                s += red[0][ty * 4 + i][tx * 4 + j];
                s += red[1][ty * 4 + i][tx * 4 + j];
                s += red[2][ty * 4 + i][tx * 4 + j];
                o[j] = s;
            }
            float4 ov = {o[0] + bv.x, o[1] + bv.y, o[2] + bv.z, o[3] + bv.w};
            *(float4*)(C + (size_t)row * N + bn + tx * 4) = ov;
        }
    }
}

// ---------------------------------------------------------------------------
// Launch. Inputs: x, edge_index, edge_attr, u, batch, W1, b1, W2, b2.
// edge_* unused; int64 inputs arrive as int32 on device.
// ---------------------------------------------------------------------------
extern "C" void kernel_launch(void* const* d_in, const int* in_sizes, int n_in,
                              void* d_out, int out_size) {
    const float* x     = (const float*)d_in[0];
    const float* u     = (const float*)d_in[3];
    const int*   batch = (const int*)d_in[4];
    const float* W1    = (const float*)d_in[5];
    const float* b1    = (const float*)d_in[6];
    const float* W2    = (const float*)d_in[7];
    const float* b2    = (const float*)d_in[8];
    float*       out   = (float*)d_out;

    void *p_concat = nullptr, *p_h = nullptr;
    cudaGetSymbolAddress(&p_concat, g_concat);
    cudaGetSymbolAddress(&p_h, g_h);

    // 1) segment mean + concat (warp-parallel bounds search), single wave
    seg_mean_kernel<<<N_GRAPHS, 256>>>(x, u, batch);

    // 2) h = relu(concat @ W1 + b1): tf32 tensor cores, 8 warps, grid 128
    gemm1_tf32_kernel<<<dim3(HIDDEN / 64, N_GRAPHS / 64), 256>>>(
        (const float*)p_concat, W1, b1, (float*)p_h);

    // 3) out = h @ W2 + b2: 32x32 tiles, 4-way in-block split-K, grid 128
    gemm2_kernel<<<dim3(F_OUT / 32, N_GRAPHS / 32), 256>>>(
        (const float*)p_h, W2, b2, out);
}